// round 4
// baseline (speedup 1.0000x reference)
#include <cuda_runtime.h>

#define NN 50000
#define HID 128
#define PCOLS 384
#define SENT ((int)0x80000000)

// Scratch (allowed: __device__ globals, no runtime allocation)
__device__ float g_P[NN * PCOLS];   // [A | B | U1] per node, 76.8 MB
__device__ int   g_M[NN * HID];     // encoded segment-max,   25.6 MB

// Order-preserving float <-> int encoding (monotonic for all finite floats & infs)
__device__ __forceinline__ int encf(float f) {
    int i = __float_as_int(f);
    return i >= 0 ? i : i ^ 0x7fffffff;
}
__device__ __forceinline__ float decf(int i) {
    return __int_as_float(i >= 0 ? i : i ^ 0x7fffffff);
}

// ---------------------------------------------------------------------------
// init: fill g_M with sentinel
// ---------------------------------------------------------------------------
__global__ void k_init(int n4) {
    int i = blockIdx.x * blockDim.x + threadIdx.x;
    if (i < n4) ((int4*)g_M)[i] = make_int4(SENT, SENT, SENT, SENT);
}

// ---------------------------------------------------------------------------
// Shared GEMM core: 128x128 tile, K processed in 32-wide chunks.
// Zs: transposed+swizzled [32 k][128 rows], Ws: [32 k][128 cols].
// 256 threads; thread (ty=tid/16, tx=tid%16) owns rows {ty*4+i, 64+ty*4+i}
// and cols {tx*4+j, 64+tx*4+j}.
// ---------------------------------------------------------------------------
__device__ __forceinline__ void mm_chunk(const float* Zs, const float* Ws,
                                         float acc[8][8], int ty, int tx) {
#pragma unroll
    for (int k = 0; k < 32; ++k) {
        int swz = (k >> 2) & 7;
        float4 a0 = *(const float4*)&Zs[k * 128 + ((ty ^ swz) << 2)];
        float4 a1 = *(const float4*)&Zs[k * 128 + (((16 + ty) ^ swz) << 2)];
        float4 b0 = *(const float4*)&Ws[k * 128 + (tx << 2)];
        float4 b1 = *(const float4*)&Ws[k * 128 + ((16 + tx) << 2)];
        float av[8] = {a0.x, a0.y, a0.z, a0.w, a1.x, a1.y, a1.z, a1.w};
        float bv[8] = {b0.x, b0.y, b0.z, b0.w, b1.x, b1.y, b1.z, b1.w};
#pragma unroll
        for (int i = 0; i < 8; ++i)
#pragma unroll
            for (int j = 0; j < 8; ++j)
                acc[i][j] = fmaf(av[i], bv[j], acc[i][j]);
    }
}

// Store one float4 of A-operand (rows of the M-dim tile) transposed+swizzled.
__device__ __forceinline__ void store_z4(float* Zs, int k_local, int kq,
                                         int r_local, float4 v) {
    int rm  = r_local & 3;
    int ccb = r_local >> 2;
    const float* pv = (const float*)&v;
#pragma unroll
    for (int j = 0; j < 4; ++j) {
        int ccs = ccb ^ kq;  // (k>>2)&7 == kq for j<4
        Zs[(k_local + j) * 128 + (ccs << 2) + rm] = pv[j];
    }
}

__device__ __forceinline__ void load_w_chunk(float* Ws, const float* __restrict__ W,
                                             int kc, int tid) {
    int c4 = (tid & 31) << 2;
#pragma unroll
    for (int it = 0; it < 4; ++it) {
        int kl = (tid >> 5) + it * 8;
        *(float4*)&Ws[kl * 128 + c4] =
            *(const float4*)&W[(kc * 32 + kl) * HID + c4];
    }
}

// ---------------------------------------------------------------------------
// GEMM 1: P[N,384] = z[N,128] @ [Wm1 | Wm2 | Wu1]   (blockIdx.y picks col-block)
// ---------------------------------------------------------------------------
__global__ void __launch_bounds__(256)
k_gemm1(const float* __restrict__ z, const float* __restrict__ Wm,
        const float* __restrict__ Wu) {
    __shared__ __align__(16) float Zs[32 * 128];
    __shared__ __align__(16) float Ws[32 * 128];
    int tid = threadIdx.x, ty = tid >> 4, tx = tid & 15;
    int rowbase = blockIdx.x * 128;
    int cb = blockIdx.y;
    const float* W = (cb == 0) ? Wm : (cb == 1 ? Wm + 128 * HID : Wu);

    float acc[8][8];
#pragma unroll
    for (int i = 0; i < 8; ++i)
#pragma unroll
        for (int j = 0; j < 8; ++j) acc[i][j] = 0.f;

    int kq = tid & 7;
    int k_local = kq << 2;
    for (int kc = 0; kc < 4; ++kc) {
        int kg = kc * 32 + k_local;
#pragma unroll
        for (int it = 0; it < 4; ++it) {
            int r_local = (tid >> 3) + it * 32;
            int row = rowbase + r_local;
            float4 v = make_float4(0.f, 0.f, 0.f, 0.f);
            if (row < NN) v = *(const float4*)&z[row * HID + kg];
            store_z4(Zs, k_local, kq, r_local, v);
        }
        load_w_chunk(Ws, W, kc, tid);
        __syncthreads();
        mm_chunk(Zs, Ws, acc, ty, tx);
        __syncthreads();
    }

#pragma unroll
    for (int i = 0; i < 8; ++i) {
        int r_local = (i < 4) ? (ty * 4 + i) : (64 + ty * 4 + i - 4);
        int row = rowbase + r_local;
        if (row < NN) {
            float* p = &g_P[row * PCOLS + cb * 128];
            float4 v0 = make_float4(acc[i][0], acc[i][1], acc[i][2], acc[i][3]);
            float4 v1 = make_float4(acc[i][4], acc[i][5], acc[i][6], acc[i][7]);
            *(float4*)&p[tx * 4] = v0;
            *(float4*)&p[64 + tx * 4] = v1;
        }
    }
}

// ---------------------------------------------------------------------------
// Edge phase: one warp per edge.
//   C = B[src] + w * r ;  atomicMax(M[dst], enc(C))
// ---------------------------------------------------------------------------
__global__ void k_edge(const int* __restrict__ src, const int* __restrict__ dst,
                       const float* __restrict__ w, const float* __restrict__ Wm,
                       int E) {
    int gw = (blockIdx.x * blockDim.x + threadIdx.x) >> 5;
    int lane = threadIdx.x & 31;
    if (gw >= E) return;
    int   s  = __ldg(&src[gw]);
    int   d  = __ldg(&dst[gw]);
    float we = __ldg(&w[gw]);
    float4 r4 = *(const float4*)&Wm[256 * HID + lane * 4];
    float4 b  = *(const float4*)&g_P[s * PCOLS + 128 + lane * 4];
    int* mp = &g_M[d * HID + lane * 4];
    atomicMax(mp + 0, encf(fmaf(we, r4.x, b.x)));
    atomicMax(mp + 1, encf(fmaf(we, r4.y, b.y)));
    atomicMax(mp + 2, encf(fmaf(we, r4.z, b.z)));
    atomicMax(mp + 3, encf(fmaf(we, r4.w, b.w)));
}

// ---------------------------------------------------------------------------
// GEMM 2: h = m @ Wu2 + U1 + bu,  with m reconstructed on the fly:
//   m[n,k] = (M[n,k]==SENT) ? 0 : A[n,k] + bm[k] + dec(M[n,k])
// ---------------------------------------------------------------------------
__global__ void __launch_bounds__(256)
k_gemm2(const float* __restrict__ Wu, const float* __restrict__ bm,
        const float* __restrict__ bu, float* __restrict__ h) {
    __shared__ __align__(16) float Zs[32 * 128];
    __shared__ __align__(16) float Ws[32 * 128];
    int tid = threadIdx.x, ty = tid >> 4, tx = tid & 15;
    int rowbase = blockIdx.x * 128;
    const float* W = Wu + 128 * HID;  // Wu2

    float acc[8][8];
#pragma unroll
    for (int i = 0; i < 8; ++i)
#pragma unroll
        for (int j = 0; j < 8; ++j) acc[i][j] = 0.f;

    int kq = tid & 7;
    int k_local = kq << 2;
    for (int kc = 0; kc < 4; ++kc) {
        int kg = kc * 32 + k_local;
        float4 bm4 = *(const float4*)&bm[kg];
#pragma unroll
        for (int it = 0; it < 4; ++it) {
            int r_local = (tid >> 3) + it * 32;
            int row = rowbase + r_local;
            float4 v = make_float4(0.f, 0.f, 0.f, 0.f);
            if (row < NN) {
                float4 a  = *(const float4*)&g_P[row * PCOLS + kg];
                int4   mm = *(const int4*)&g_M[row * HID + kg];
                v.x = (mm.x == SENT) ? 0.f : a.x + bm4.x + decf(mm.x);
                v.y = (mm.y == SENT) ? 0.f : a.y + bm4.y + decf(mm.y);
                v.z = (mm.z == SENT) ? 0.f : a.z + bm4.z + decf(mm.z);
                v.w = (mm.w == SENT) ? 0.f : a.w + bm4.w + decf(mm.w);
            }
            store_z4(Zs, k_local, kq, r_local, v);
        }
        load_w_chunk(Ws, W, kc, tid);
        __syncthreads();
        mm_chunk(Zs, Ws, acc, ty, tx);
        __syncthreads();
    }

#pragma unroll
    for (int i = 0; i < 8; ++i) {
        int r_local = (i < 4) ? (ty * 4 + i) : (64 + ty * 4 + i - 4);
        int row = rowbase + r_local;
        if (row < NN) {
            const float* u = &g_P[row * PCOLS + 256];
            float4 u0  = *(const float4*)&u[tx * 4];
            float4 u1  = *(const float4*)&u[64 + tx * 4];
            float4 bu0 = *(const float4*)&bu[tx * 4];
            float4 bu1 = *(const float4*)&bu[64 + tx * 4];
            float4 v0 = make_float4(acc[i][0] + u0.x + bu0.x, acc[i][1] + u0.y + bu0.y,
                                    acc[i][2] + u0.z + bu0.z, acc[i][3] + u0.w + bu0.w);
            float4 v1 = make_float4(acc[i][4] + u1.x + bu1.x, acc[i][5] + u1.y + bu1.y,
                                    acc[i][6] + u1.z + bu1.z, acc[i][7] + u1.w + bu1.w);
            *(float4*)&h[row * HID + tx * 4] = v0;
            *(float4*)&h[row * HID + 64 + tx * 4] = v1;
        }
    }
}

// ---------------------------------------------------------------------------
extern "C" void kernel_launch(void* const* d_in, const int* in_sizes, int n_in,
                              void* d_out, int out_size) {
    const float* z   = (const float*)d_in[0];
    const float* w   = (const float*)d_in[1];
    const int*   src = (const int*)d_in[2];
    const int*   dst = (const int*)d_in[3];
    const float* Wm  = (const float*)d_in[4];
    const float* bm  = (const float*)d_in[5];
    const float* Wu  = (const float*)d_in[6];
    const float* bu  = (const float*)d_in[7];
    float* h = (float*)d_out;
    int E = in_sizes[2];

    int n4 = NN * HID / 4;
    k_init<<<(n4 + 255) / 256, 256>>>(n4);

    dim3 g1((NN + 127) / 128, 3);
    k_gemm1<<<g1, 256>>>(z, Wm, Wu);

    int eblocks = (E * 32 + 255) / 256;
    k_edge<<<eblocks, 256>>>(src, dst, w, Wm, E);

    k_gemm2<<<(NN + 127) / 128, 256>>>(Wu, bm, bu, h);
}